// round 3
// baseline (speedup 1.0000x reference)
#include <cuda_runtime.h>
#include <cstdint>

// Unfold (im2col): x[B=32, C=64, H=64, W=64] f32, K=3x3, stride=1
//   -> out[B=32, C*9=576, L=62*62=3844] f32
//
// Block = (channel bc, l-chunk). Each block writes all 9 kernel-offset rows
// for its l-range:  out[(bc*9+k)][l] = src[ki*64+kj + l + 2*(l/62)].
// The 9 loads per l come from a ~130-float window -> the 16KB channel streams
// through L1 once per block and the 9x reuse is served by L1, cutting L2 read
// traffic ~9x (L2 was the binding resource at ~9.7 TB/s).

#define HW     64
#define CH     (HW * HW)      // 4096 floats per channel
#define WO     62
#define L      (WO * WO)      // 3844
#define NCHUNK 4
#define LCHUNK (L / NCHUNK)   // 961 = 3*256 + 193

__global__ __launch_bounds__(256)
void unfold_kernel(const float* __restrict__ x, float* __restrict__ out)
{
    const int bc = blockIdx.x;                      // 0..2047 (b*64+c)
    const float* __restrict__ src = x + (size_t)bc * CH;
    float* __restrict__ dst       = out + (size_t)bc * 9 * L;

    int l = blockIdx.y * LCHUNK + threadIdx.x;
    const int lend = blockIdx.y * LCHUNK + LCHUNK;

#pragma unroll 4
    for (; l < lend; l += 256) {
        const int i = l / WO;                       // const divisor -> mulhi
        const int a = l + 2 * i;                    // input offset for (ki,kj)=(0,0)
#pragma unroll
        for (int k = 0; k < 9; ++k) {
            const int ki = k / 3;                   // constants after unroll
            const int kj = k - ki * 3;
            dst[k * L + l] = src[ki * HW + kj + a];
        }
    }
}

extern "C" void kernel_launch(void* const* d_in, const int* in_sizes, int n_in,
                              void* d_out, int out_size)
{
    const float* x = (const float*)d_in[0];
    float* out = (float*)d_out;

    dim3 grid(2048, NCHUNK, 1);                     // 32*64 channels x 4 l-chunks
    unfold_kernel<<<grid, 256>>>(x, out);
}

// round 4
// speedup vs baseline: 1.1053x; 1.1053x over previous
#include <cuda_runtime.h>
#include <cstdint>

// Unfold (im2col): x[32,64,64,64] f32, 3x3/s1 -> out[32,576,3844] f32
// out[(bc*9+k)][l] = ch[ki*64+kj + l + 2*(l/62)],  ch = channel bc (4096 floats)
//
// R2 was LSU-bound on STG.32 issue cost (~5 cyc per warp store = ~75K cyc/SM).
// Here: stage channel in smem, assemble output rows in smem (conflict-free
// LDS/STS), and store rows with cp.async.bulk (TMA) -> near-zero SM issue
// cost per stored byte. DRAM write (283 MB) becomes the binding resource.

#define HW        64
#define CH        4096
#define WO        62
#define L         3844
#define SPLIT     1920                  // chunk0=[0,1920) chunk1=[1920,3844); both *4B are 16B-multiples
#define ROWPITCH  1952                  // floats; 7808 B, 128B-multiple, >= 1924
#define ROWS_OFF  CH                    // rows start at float index 4096 (byte 16384, 16B aligned)
#define SMEM_FLOATS (CH + 9 * ROWPITCH) // 21664 floats = 86656 B

extern __shared__ float smem[];

__device__ __forceinline__ uint32_t smem_u32(const void* p) {
    uint32_t a;
    asm("{ .reg .u64 t; cvta.to.shared.u64 t, %1; cvt.u32.u64 %0, t; }"
        : "=r"(a) : "l"(p));
    return a;
}

__global__ __launch_bounds__(256)
void unfold_kernel(const float* __restrict__ x, float* __restrict__ out)
{
    const int bc   = blockIdx.x;              // 0..2047
    const int half = blockIdx.y;              // 0..1
    const int l0   = half ? SPLIT : 0;
    const int l1   = half ? L : SPLIT;
    const int tid  = threadIdx.x;

    // ---- stage channel (16 KB) into smem, coalesced float4 ----
    {
        const float4* __restrict__ s4 = reinterpret_cast<const float4*>(x + (size_t)bc * CH);
        float4* d4 = reinterpret_cast<float4*>(smem);
#pragma unroll
        for (int v = tid; v < CH / 4; v += 256) d4[v] = s4[v];
    }
    __syncthreads();

    const uint32_t rows_base = smem_u32(smem) + ROWS_OFF * 4;
    const uint32_t bytes = (uint32_t)(l1 - l0) * 4;   // 7680 or 7696

    // ---- assemble each row chunk in smem, then TMA bulk-store it ----
    for (int k = 0; k < 9; ++k) {
        const int ki = k / 3;
        const int kj = k - 3 * ki;
        float* rowbuf = smem + ROWS_OFF + k * ROWPITCH;
        const float* ch = smem + ki * HW + kj;

#pragma unroll 4
        for (int l = l0 + tid; l < l1; l += 256) {
            const int i = l / WO;                     // const divisor -> mulhi
            rowbuf[l - l0] = ch[l + 2 * i];           // LDS + STS, conflict-free
        }
        __syncthreads();

        if (tid == 0) {
            asm volatile("fence.proxy.async.shared::cta;" ::: "memory");
            const float* g = out + ((size_t)bc * 9 + k) * L + l0;
            const uint32_t s = rows_base + (uint32_t)k * (ROWPITCH * 4);
            asm volatile(
                "cp.async.bulk.global.shared::cta.bulk_group [%0], [%1], %2;"
                :: "l"(g), "r"(s), "r"(bytes) : "memory");
            asm volatile("cp.async.bulk.commit_group;" ::: "memory");
        }
    }

    // drain all bulk stores before smem is deallocated at block exit
    if (tid == 0)
        asm volatile("cp.async.bulk.wait_group 0;" ::: "memory");
    __syncthreads();
}

extern "C" void kernel_launch(void* const* d_in, const int* in_sizes, int n_in,
                              void* d_out, int out_size)
{
    const float* x = (const float*)d_in[0];
    float* out = (float*)d_out;

    static_assert(SMEM_FLOATS * 4 == 86656, "smem size");
    cudaFuncSetAttribute(unfold_kernel,
                         cudaFuncAttributeMaxDynamicSharedMemorySize,
                         SMEM_FLOATS * 4);

    dim3 grid(2048, 2, 1);                    // (b*c, half-of-L)
    unfold_kernel<<<grid, 256, SMEM_FLOATS * 4>>>(x, out);
}

// round 5
// speedup vs baseline: 1.5217x; 1.3767x over previous
#include <cuda_runtime.h>
#include <cstdint>

// Unfold (im2col): x[32,64,64,64] f32, 3x3/s1 -> out[32,576,3844] f32
// out[(bc*9+k)][62i+j] = ch[64i + j + 64ki + kj],  ch = channel bc.
//
// Block = one channel. Stage 16KB channel into smem with pitch-33 padding
// (bank = (row+col)%32 -> the stride-4-word gather reads are conflict-free).
// Each thread builds one output float4 with 4 LDS.32 and writes one STG.128.
// dst float4 index for (k,m) is exactly t = k*961+m -> contiguous stores.

#define HW    64
#define CH    4096
#define WO    62
#define L     3844
#define NV4   961            // float4 per output row (961*4 == 3844, no tail)
#define TOT   (9 * NV4)      // 8649 float4 per channel
#define SMW   4224           // 4096 + 4096/32 padding

__device__ __forceinline__ int PADI(int w) { return w + (w >> 5); }

__global__ __launch_bounds__(256)
void unfold_kernel(const float* __restrict__ x, float* __restrict__ out)
{
    __shared__ float sm[SMW];

    const int bc  = blockIdx.x;               // 0..2047
    const int tid = threadIdx.x;

    // ---- stage channel into padded smem (4 LDG.128 / thread) ----
    {
        const float4* __restrict__ s4 =
            reinterpret_cast<const float4*>(x + (size_t)bc * CH);
#pragma unroll
        for (int v = tid; v < CH / 4; v += 256) {
            float4 d = s4[v];
            int w = 4 * v;
            sm[PADI(w + 0)] = d.x;
            sm[PADI(w + 1)] = d.y;
            sm[PADI(w + 2)] = d.z;
            sm[PADI(w + 3)] = d.w;
        }
    }
    __syncthreads();

    float4* __restrict__ dst4 =
        reinterpret_cast<float4*>(out + (size_t)bc * 9 * L);

    // TOT = 8649 = 33*256 + 201
#pragma unroll 3
    for (int t = tid; t < TOT; t += 256) {
        const int k  = t / NV4;               // 0..8   (const-div -> mulhi)
        const int m  = t - k * NV4;
        const int ki = k / 3;
        const int kj = k - 3 * ki;
        const int off = ki * HW + kj;

        const int l  = 4 * m;
        const int i0 = l / WO;                // mulhi (l even -> j0 even)
        const int j0 = l - WO * i0;
        const int w0 = off + l + 2 * i0;
        const int cr = (j0 == 60) ? 2 : 0;    // only z,w can cross a row end

        float4 v;
        v.x = sm[PADI(w0 + 0)];
        v.y = sm[PADI(w0 + 1)];
        v.z = sm[PADI(w0 + 2 + cr)];
        v.w = sm[PADI(w0 + 3 + cr)];

        dst4[t] = v;                          // word off = k*L + l  (16B aligned)
    }
}

extern "C" void kernel_launch(void* const* d_in, const int* in_sizes, int n_in,
                              void* d_out, int out_size)
{
    const float* x = (const float*)d_in[0];
    float* out = (float*)d_out;

    unfold_kernel<<<2048, 256>>>(x, out);     // one block per (b,c) channel
}

// round 6
// speedup vs baseline: 1.5604x; 1.0255x over previous
#include <cuda_runtime.h>
#include <cstdint>

// Unfold (im2col): x[32,64,64,64] f32, 3x3/s1 -> out[32,576,3844] f32
// out[(bc*9+k)][l+e] = ch[ki*64 + kj + (l+e) + 2*floor((l+e)/62)]
//
// Block = one channel staged in pitch-33 padded smem (conflict-free gather).
// Thread handles float4 m for ALL 9 k's: per (m,ki) the 12 needed elements
// (kj=0..2, e=0..3) all come from the 8-word window C..C+7,
//   word(kj,e) = C + kj + e + ((j0==60 && e>=2) ? 2 : 0),  C = ki*64 + l + 2*i0
// -> 8 LDS + 6 SEL + 3 STG.128 replaces 12 LDS + 12 addr-calcs + repeated
// divides. Index math (l/62, j0, crossing) hoisted out of the k loop.

#define HW    64
#define CH    4096
#define WO    62
#define L     3844
#define NV4   961             // float4 per output row
#define SMW   4240            // 4096 + 128 pad + slack for C+7 overread

__device__ __forceinline__ int PADI(int w) { return w + (w >> 5); }

__global__ __launch_bounds__(256)
void unfold_kernel(const float* __restrict__ x, float* __restrict__ out)
{
    __shared__ float sm[SMW];

    const int bc  = blockIdx.x;               // 0..2047
    const int tid = threadIdx.x;

    // ---- stage channel into padded smem ----
    {
        const float4* __restrict__ s4 =
            reinterpret_cast<const float4*>(x + (size_t)bc * CH);
#pragma unroll
        for (int v = tid; v < CH / 4; v += 256) {
            float4 d = s4[v];
            int w = 4 * v;
            sm[PADI(w + 0)] = d.x;
            sm[PADI(w + 1)] = d.y;
            sm[PADI(w + 2)] = d.z;
            sm[PADI(w + 3)] = d.w;
        }
    }
    __syncthreads();

    float4* __restrict__ dst4 =
        reinterpret_cast<float4*>(out + (size_t)bc * 9 * L);

    // 961 = 3*256 + 193
#pragma unroll
    for (int it = 0; it < 4; ++it) {
        const int m = tid + 256 * it;
        if (m < NV4) {
            const int l    = 4 * m;
            const int i0   = l / WO;          // const divisor -> mulhi
            const int j0   = l - WO * i0;
            const int base = l + 2 * i0;
            const bool cr  = (j0 == 60);      // only e=2,3 can cross, +2 words

#pragma unroll
            for (int ki = 0; ki < 3; ++ki) {
                const int C = ki * HW + base;

                const float s0 = sm[PADI(C + 0)];
                const float s1 = sm[PADI(C + 1)];
                const float s2 = sm[PADI(C + 2)];
                const float s3 = sm[PADI(C + 3)];
                const float s4 = sm[PADI(C + 4)];
                const float s5 = sm[PADI(C + 5)];
                const float s6 = sm[PADI(C + 6)];
                const float s7 = sm[PADI(C + 7)];

                float4 v;
                // kj = 0
                v.x = s0; v.y = s1;
                v.z = cr ? s4 : s2; v.w = cr ? s5 : s3;
                dst4[(3 * ki + 0) * NV4 + m] = v;
                // kj = 1
                v.x = s1; v.y = s2;
                v.z = cr ? s5 : s3; v.w = cr ? s6 : s4;
                dst4[(3 * ki + 1) * NV4 + m] = v;
                // kj = 2
                v.x = s2; v.y = s3;
                v.z = cr ? s6 : s4; v.w = cr ? s7 : s5;
                dst4[(3 * ki + 2) * NV4 + m] = v;
            }
        }
    }
}

extern "C" void kernel_launch(void* const* d_in, const int* in_sizes, int n_in,
                              void* d_out, int out_size)
{
    const float* x = (const float*)d_in[0];
    float* out = (float*)d_out;

    unfold_kernel<<<2048, 256>>>(x, out);     // one block per (b,c) channel
}